// round 1
// baseline (speedup 1.0000x reference)
#include <cuda_runtime.h>

#define Nn 50000
#define Ee 800000
#define ETOT (Ee + Nn)
#define NEG 0.2f

// ---------------- scratch (device globals; no runtime allocation) ----------
__device__ float    g_xl[(size_t)Nn * 128];
__device__ float    g_xr[(size_t)Nn * 128];
__device__ float    g_acc[(size_t)Nn * 128];
__device__ float    g_h[(size_t)Nn * 128];
__device__ float    g_logits[(size_t)ETOT * 4];
__device__ float    g_expe[(size_t)ETOT * 4];
__device__ unsigned g_maxkey[Nn * 4];
__device__ float    g_sum[Nn * 4];
__device__ float    g_lsum[Nn];
__device__ float    g_lcnt[Nn];
__device__ float    g_lattr[Nn];

// ---------------- helpers ---------------------------------------------------
__device__ __forceinline__ unsigned fkey(float f) {
    unsigned u = __float_as_uint(f);
    return (u & 0x80000000u) ? ~u : (u | 0x80000000u);
}
__device__ __forceinline__ float funkey(unsigned k) {
    return (k & 0x80000000u) ? __uint_as_float(k ^ 0x80000000u)
                             : __uint_as_float(~k);
}
__device__ __forceinline__ void red_add_v4(float* p, float4 v) {
    asm volatile("red.global.add.v4.f32 [%0], {%1,%2,%3,%4};"
                 :: "l"(p), "f"(v.x), "f"(v.y), "f"(v.z), "f"(v.w)
                 : "memory");
}
__device__ __forceinline__ float lrelu(float v) {
    return (v > 0.f) ? v : NEG * v;
}

// ---------------- self-loop attr (mean of incoming edge attrs) --------------
__global__ void zero_loop_k() {
    int i = blockIdx.x * blockDim.x + threadIdx.x;
    if (i < Nn) { g_lsum[i] = 0.f; g_lcnt[i] = 0.f; }
}
__global__ void loop_accum_k(const int* __restrict__ ei, const float* __restrict__ ea) {
    int e = blockIdx.x * blockDim.x + threadIdx.x;
    if (e < Ee) {
        int dst = ei[Ee + e];
        atomicAdd(&g_lsum[dst], ea[e]);
        atomicAdd(&g_lcnt[dst], 1.f);
    }
}
__global__ void loop_fin_k() {
    int n = blockIdx.x * blockDim.x + threadIdx.x;
    if (n < Nn) {
        float c = g_lcnt[n];
        g_lattr[n] = (c > 0.f) ? g_lsum[n] / c : 0.f;
    }
}

// ---------------- per-layer zero init ---------------------------------------
__global__ void zero_layer_k() {
    int i = blockIdx.x * blockDim.x + threadIdx.x;
    if (i < Nn * 128) g_acc[i] = 0.f;
    if (i < Nn * 4) { g_maxkey[i] = 0u; g_sum[i] = 0.f; }
}

// ---------------- SGEMM: C[M][128] = A[M][128] @ W[128][128] + bias ---------
__global__ void __launch_bounds__(256, 2)
gemm128_k(const float* __restrict__ A, const float* __restrict__ W,
          const float* __restrict__ bias, float* __restrict__ Cm,
          int M, int relu) {
    __shared__ float As[8][128];
    __shared__ float Bs[8][128];
    const int t = threadIdx.x;
    const int row0 = blockIdx.x * 128;
    const int ty = t >> 4, tx = t & 15;

    float acc[8][8];
#pragma unroll
    for (int i = 0; i < 8; i++)
#pragma unroll
        for (int j = 0; j < 8; j++) acc[i][j] = 0.f;

    const int lr = t >> 1;          // A-load row within tile 0..127
    const int lk = (t & 1) * 4;     // 0 or 4

    for (int k0 = 0; k0 < 128; k0 += 8) {
        // A tile -> transposed smem
        int gr = row0 + lr;
        float4 av = make_float4(0.f, 0.f, 0.f, 0.f);
        if (gr < M) av = *(const float4*)(A + (size_t)gr * 128 + k0 + lk);
        As[lk + 0][lr] = av.x; As[lk + 1][lr] = av.y;
        As[lk + 2][lr] = av.z; As[lk + 3][lr] = av.w;
        // B tile (8x128 contiguous)
        {
            int kk = t >> 5;
            int c  = (t & 31) * 4;
            *(float4*)&Bs[kk][c] = *(const float4*)(W + (size_t)(k0 + kk) * 128 + c);
        }
        __syncthreads();
#pragma unroll
        for (int kk = 0; kk < 8; kk++) {
            float a[8], b[8];
            *(float4*)&a[0] = *(const float4*)&As[kk][ty * 8];
            *(float4*)&a[4] = *(const float4*)&As[kk][ty * 8 + 4];
            *(float4*)&b[0] = *(const float4*)&Bs[kk][tx * 8];
            *(float4*)&b[4] = *(const float4*)&Bs[kk][tx * 8 + 4];
#pragma unroll
            for (int i = 0; i < 8; i++)
#pragma unroll
                for (int j = 0; j < 8; j++) acc[i][j] = fmaf(a[i], b[j], acc[i][j]);
        }
        __syncthreads();
    }

    float bj[8];
#pragma unroll
    for (int j = 0; j < 8; j++) bj[j] = bias[tx * 8 + j];

#pragma unroll
    for (int i = 0; i < 8; i++) {
        int gr = row0 + ty * 8 + i;
        if (gr < M) {
            float o[8];
#pragma unroll
            for (int j = 0; j < 8; j++) {
                o[j] = acc[i][j] + bj[j];
                if (relu) o[j] = fmaxf(o[j], 0.f);
            }
            *(float4*)(Cm + (size_t)gr * 128 + tx * 8)     = make_float4(o[0], o[1], o[2], o[3]);
            *(float4*)(Cm + (size_t)gr * 128 + tx * 8 + 4) = make_float4(o[4], o[5], o[6], o[7]);
        }
    }
}

// ---------------- edge pass 1: logits + segment max -------------------------
// one warp per edge; lane holds 4 consecutive channels (all same head)
__global__ void edge_logits_k(const int* __restrict__ ei, const float* __restrict__ ea,
                              const float* __restrict__ We, const float* __restrict__ att) {
    int warp = (blockIdx.x * blockDim.x + threadIdx.x) >> 5;
    int lane = threadIdx.x & 31;
    if (warp >= ETOT) return;
    int src, dst; float attr;
    if (warp < Ee) { src = ei[warp]; dst = ei[Ee + warp]; attr = ea[warp]; }
    else           { src = warp - Ee; dst = src; attr = g_lattr[src]; }

    float4 a  = *(const float4*)(g_xl + (size_t)src * 128 + lane * 4);
    float4 b  = *(const float4*)(g_xr + (size_t)dst * 128 + lane * 4);
    float4 w  = *(const float4*)(We  + lane * 4);
    float4 at = *(const float4*)(att + lane * 4);

    float p;
    {
        float m0 = lrelu(a.x + b.x + attr * w.x);
        float m1 = lrelu(a.y + b.y + attr * w.y);
        float m2 = lrelu(a.z + b.z + attr * w.z);
        float m3 = lrelu(a.w + b.w + attr * w.w);
        p = m0 * at.x + m1 * at.y + m2 * at.z + m3 * at.w;
    }
    p += __shfl_xor_sync(0xFFFFFFFFu, p, 1);
    p += __shfl_xor_sync(0xFFFFFFFFu, p, 2);
    p += __shfl_xor_sync(0xFFFFFFFFu, p, 4);
    if ((lane & 7) == 0) {
        int head = lane >> 3;
        g_logits[(size_t)warp * 4 + head] = p;
        atomicMax(&g_maxkey[dst * 4 + head], fkey(p));
    }
}

// ---------------- edge pass 2: exp + segment sum ----------------------------
__global__ void edge_expsum_k(const int* __restrict__ ei) {
    int i = blockIdx.x * blockDim.x + threadIdx.x;
    if (i >= ETOT * 4) return;
    int e = i >> 2, h = i & 3;
    int dst = (e < Ee) ? ei[Ee + e] : (e - Ee);
    float mx = funkey(g_maxkey[dst * 4 + h]);
    float v = __expf(g_logits[i] - mx);
    g_expe[i] = v;
    atomicAdd(&g_sum[dst * 4 + h], v);
}

// ---------------- edge pass 3: weighted aggregate ---------------------------
__global__ void edge_agg_k(const int* __restrict__ ei) {
    int warp = (blockIdx.x * blockDim.x + threadIdx.x) >> 5;
    int lane = threadIdx.x & 31;
    if (warp >= ETOT) return;
    int src, dst;
    if (warp < Ee) { src = ei[warp]; dst = ei[Ee + warp]; }
    else           { src = warp - Ee; dst = src; }
    int head = lane >> 3;
    float alpha = g_expe[(size_t)warp * 4 + head] /
                  (g_sum[dst * 4 + head] + 1e-16f);
    float4 v = *(const float4*)(g_xl + (size_t)src * 128 + lane * 4);
    v.x *= alpha; v.y *= alpha; v.z *= alpha; v.w *= alpha;
    red_add_v4(g_acc + (size_t)dst * 128 + lane * 4, v);
}

// ---------------- epilogue: + bias_out, relu, -> h --------------------------
__global__ void bias_relu_k(const float* __restrict__ bo) {
    int i = blockIdx.x * blockDim.x + threadIdx.x;
    if (i < Nn * 128) g_h[i] = fmaxf(g_acc[i] + bo[i & 127], 0.f);
}

// ---------------- launch ----------------------------------------------------
extern "C" void kernel_launch(void* const* d_in, const int* in_sizes, int n_in,
                              void* d_out, int out_size) {
    const float* x    = (const float*)d_in[0];
    const int*   ei   = (const int*)  d_in[1];
    const float* ea   = (const float*)d_in[2];
    const float* Wl1  = (const float*)d_in[3];
    const float* bl1  = (const float*)d_in[4];
    const float* Wr1  = (const float*)d_in[5];
    const float* br1  = (const float*)d_in[6];
    const float* We1  = (const float*)d_in[7];
    const float* att1 = (const float*)d_in[8];
    const float* bo1  = (const float*)d_in[9];
    const float* Wl2  = (const float*)d_in[10];
    const float* bl2  = (const float*)d_in[11];
    const float* Wr2  = (const float*)d_in[12];
    const float* br2  = (const float*)d_in[13];
    const float* We2  = (const float*)d_in[14];
    const float* att2 = (const float*)d_in[15];
    const float* bo2  = (const float*)d_in[16];
    const float* Wlin = (const float*)d_in[17];
    const float* blin = (const float*)d_in[18];
    float* out = (float*)d_out;

    float *pxl, *pxr, *ph;
    cudaGetSymbolAddress((void**)&pxl, g_xl);
    cudaGetSymbolAddress((void**)&pxr, g_xr);
    cudaGetSymbolAddress((void**)&ph,  g_h);

    const int TB = 256;
    const int gb_n    = (Nn + TB - 1) / TB;
    const int gb_e    = (Ee + TB - 1) / TB;
    const int gb_nf   = (Nn * 128 + TB - 1) / TB;
    const int gb_warp = (ETOT + 7) / 8;            // 8 warps (edges) / block
    const int gb_eh   = (ETOT * 4 + TB - 1) / TB;
    const int gb_gemm = (Nn + 127) / 128;

    // self-loop attrs
    zero_loop_k<<<gb_n, TB>>>();
    loop_accum_k<<<gb_e, TB>>>(ei, ea);
    loop_fin_k<<<gb_n, TB>>>();

    // ---- layer 1 ----
    gemm128_k<<<gb_gemm, TB>>>(x, Wl1, bl1, pxl, Nn, 0);
    gemm128_k<<<gb_gemm, TB>>>(x, Wr1, br1, pxr, Nn, 0);
    zero_layer_k<<<gb_nf, TB>>>();
    edge_logits_k<<<gb_warp, TB>>>(ei, ea, We1, att1);
    edge_expsum_k<<<gb_eh, TB>>>(ei);
    edge_agg_k<<<gb_warp, TB>>>(ei);
    bias_relu_k<<<gb_nf, TB>>>(bo1);

    // ---- layer 2 ----
    gemm128_k<<<gb_gemm, TB>>>(ph, Wl2, bl2, pxl, Nn, 0);
    gemm128_k<<<gb_gemm, TB>>>(ph, Wr2, br2, pxr, Nn, 0);
    zero_layer_k<<<gb_nf, TB>>>();
    edge_logits_k<<<gb_warp, TB>>>(ei, ea, We2, att2);
    edge_expsum_k<<<gb_eh, TB>>>(ei);
    edge_agg_k<<<gb_warp, TB>>>(ei);
    bias_relu_k<<<gb_nf, TB>>>(bo2);

    // ---- final linear + relu -> d_out ----
    gemm128_k<<<gb_gemm, TB>>>(ph, Wlin, blin, out, Nn, 1);
}

// round 2
// speedup vs baseline: 1.5316x; 1.5316x over previous
#include <cuda_runtime.h>

#define Nn 50000
#define Ee 800000
#define ETOT (Ee + Nn)
#define NEG 0.2f

// ---------------- scratch (device globals; no runtime allocation) ----------
__device__ float    g_xl[(size_t)Nn * 128];
__device__ float    g_xr[(size_t)Nn * 128];
__device__ float    g_acc[(size_t)Nn * 128];
__device__ float    g_h[(size_t)Nn * 128];
__device__ float    g_sum[Nn * 4];
__device__ float    g_lsum[Nn];
__device__ float    g_lcnt[Nn];
__device__ float    g_lattr[Nn];

// ---------------- helpers ---------------------------------------------------
__device__ __forceinline__ void red_add_v4(float* p, float4 v) {
    asm volatile("red.global.add.v4.f32 [%0], {%1,%2,%3,%4};"
                 :: "l"(p), "f"(v.x), "f"(v.y), "f"(v.z), "f"(v.w)
                 : "memory");
}
__device__ __forceinline__ float lrelu(float v) {
    return (v > 0.f) ? v : NEG * v;
}

// ---------------- self-loop attr (mean of incoming edge attrs) --------------
__global__ void zero_loop_k() {
    int i = blockIdx.x * blockDim.x + threadIdx.x;
    if (i < Nn) { g_lsum[i] = 0.f; g_lcnt[i] = 0.f; }
}
__global__ void loop_accum_k(const int* __restrict__ ei, const float* __restrict__ ea) {
    int e = blockIdx.x * blockDim.x + threadIdx.x;
    if (e < Ee) {
        int dst = ei[Ee + e];
        atomicAdd(&g_lsum[dst], ea[e]);
        atomicAdd(&g_lcnt[dst], 1.f);
    }
}
__global__ void loop_fin_k() {
    int n = blockIdx.x * blockDim.x + threadIdx.x;
    if (n < Nn) {
        float c = g_lcnt[n];
        g_lattr[n] = (c > 0.f) ? g_lsum[n] / c : 0.f;
    }
}

// ---------------- SGEMM (double-buffered): C = A @ W + bias -----------------
// 128x128 tile, 256 threads, 8x8 microtile. blockIdx.y selects (W0,C0)/(W1,C1).
__global__ void __launch_bounds__(256, 2)
gemm2_k(const float* __restrict__ A,
        const float* __restrict__ W0, const float* __restrict__ b0, float* __restrict__ C0,
        const float* __restrict__ W1, const float* __restrict__ b1, float* __restrict__ C1,
        int M, int relu) {
    const float* W    = blockIdx.y ? W1 : W0;
    const float* bias = blockIdx.y ? b1 : b0;
    float*       Cm   = blockIdx.y ? C1 : C0;

    __shared__ float As[2][8][128];
    __shared__ float Bs[2][8][128];
    const int t = threadIdx.x;
    const int row0 = blockIdx.x * 128;
    const int ty = t >> 4, tx = t & 15;

    float acc[8][8];
#pragma unroll
    for (int i = 0; i < 8; i++)
#pragma unroll
        for (int j = 0; j < 8; j++) acc[i][j] = 0.f;

    const int lr = t >> 1;          // A-load row within tile 0..127
    const int lk = (t & 1) * 4;     // 0 or 4
    const int bk = t >> 5;          // B-load k row 0..7
    const int bc = (t & 31) * 4;    // B-load col

    const int gr = row0 + lr;
    const bool arow_ok = (gr < M);

    // preload tile 0
    {
        float4 av = make_float4(0.f, 0.f, 0.f, 0.f);
        if (arow_ok) av = *(const float4*)(A + (size_t)gr * 128 + lk);
        As[0][lk + 0][lr] = av.x; As[0][lk + 1][lr] = av.y;
        As[0][lk + 2][lr] = av.z; As[0][lk + 3][lr] = av.w;
        *(float4*)&Bs[0][bk][bc] = *(const float4*)(W + (size_t)bk * 128 + bc);
    }
    __syncthreads();

    int buf = 0;
    for (int k0 = 0; k0 < 128; k0 += 8) {
        float4 av2, bv2;
        const bool more = (k0 + 8 < 128);
        if (more) {
            av2 = make_float4(0.f, 0.f, 0.f, 0.f);
            if (arow_ok) av2 = *(const float4*)(A + (size_t)gr * 128 + k0 + 8 + lk);
            bv2 = *(const float4*)(W + (size_t)(k0 + 8 + bk) * 128 + bc);
        }
#pragma unroll
        for (int kk = 0; kk < 8; kk++) {
            float a[8], b[8];
            *(float4*)&a[0] = *(const float4*)&As[buf][kk][ty * 8];
            *(float4*)&a[4] = *(const float4*)&As[buf][kk][ty * 8 + 4];
            *(float4*)&b[0] = *(const float4*)&Bs[buf][kk][tx * 8];
            *(float4*)&b[4] = *(const float4*)&Bs[buf][kk][tx * 8 + 4];
#pragma unroll
            for (int i = 0; i < 8; i++)
#pragma unroll
                for (int j = 0; j < 8; j++) acc[i][j] = fmaf(a[i], b[j], acc[i][j]);
        }
        if (more) {
            int nb = buf ^ 1;
            As[nb][lk + 0][lr] = av2.x; As[nb][lk + 1][lr] = av2.y;
            As[nb][lk + 2][lr] = av2.z; As[nb][lk + 3][lr] = av2.w;
            *(float4*)&Bs[nb][bk][bc] = bv2;
        }
        __syncthreads();
        buf ^= 1;
    }

    float bj[8];
#pragma unroll
    for (int j = 0; j < 8; j++) bj[j] = bias[tx * 8 + j];

#pragma unroll
    for (int i = 0; i < 8; i++) {
        int orow = row0 + ty * 8 + i;
        if (orow < M) {
            float o[8];
#pragma unroll
            for (int j = 0; j < 8; j++) {
                o[j] = acc[i][j] + bj[j];
                if (relu) o[j] = fmaxf(o[j], 0.f);
            }
            *(float4*)(Cm + (size_t)orow * 128 + tx * 8)     = make_float4(o[0], o[1], o[2], o[3]);
            *(float4*)(Cm + (size_t)orow * 128 + tx * 8 + 4) = make_float4(o[4], o[5], o[6], o[7]);
        }
    }
}

// ---------------- fused edge pass: logit -> exp -> unnormalized agg ---------
// One warp per edge. No max subtraction (mathematically invariant in softmax;
// logits here are O(10) << 88, every node has a self-loop).
__global__ void edge_fused_k(const int* __restrict__ ei, const float* __restrict__ ea,
                             const float* __restrict__ We, const float* __restrict__ att) {
    int warp = (blockIdx.x * blockDim.x + threadIdx.x) >> 5;
    int lane = threadIdx.x & 31;
    if (warp >= ETOT) return;
    int src, dst; float attr;
    if (warp < Ee) { src = ei[warp]; dst = ei[Ee + warp]; attr = ea[warp]; }
    else           { src = warp - Ee; dst = src; attr = g_lattr[src]; }

    float4 a  = *(const float4*)(g_xl + (size_t)src * 128 + lane * 4);
    float4 b  = *(const float4*)(g_xr + (size_t)dst * 128 + lane * 4);
    float4 w  = *(const float4*)(We  + lane * 4);
    float4 at = *(const float4*)(att + lane * 4);

    float p;
    {
        float m0 = lrelu(a.x + b.x + attr * w.x);
        float m1 = lrelu(a.y + b.y + attr * w.y);
        float m2 = lrelu(a.z + b.z + attr * w.z);
        float m3 = lrelu(a.w + b.w + attr * w.w);
        p = m0 * at.x + m1 * at.y + m2 * at.z + m3 * at.w;
    }
    // butterfly within each 8-lane head group: every lane gets its head's logit
    p += __shfl_xor_sync(0xFFFFFFFFu, p, 1);
    p += __shfl_xor_sync(0xFFFFFFFFu, p, 2);
    p += __shfl_xor_sync(0xFFFFFFFFu, p, 4);

    float e = __expf(p);

    // unnormalized weighted aggregate: acc[dst] += e * xl[src]
    float4 v = make_float4(a.x * e, a.y * e, a.z * e, a.w * e);
    red_add_v4(g_acc + (size_t)dst * 128 + lane * 4, v);

    // per-head normalizer: sum[dst][h] += e_h   (lane h in 0..3 grabs head h's e)
    float eh = __shfl_sync(0xFFFFFFFFu, e, lane * 8);
    if (lane < 4) atomicAdd(&g_sum[dst * 4 + lane], eh);
}

// ---------------- epilogue: normalize + bias + relu -> h --------------------
__global__ void norm_bias_relu_k(const float* __restrict__ bo) {
    int i = blockIdx.x * blockDim.x + threadIdx.x;
    if (i >= Nn * 128) return;
    int n = i >> 7, c = i & 127, h = c >> 5;
    float s = g_sum[n * 4 + h] + 1e-16f;
    g_h[i] = fmaxf(g_acc[i] / s + bo[c], 0.f);
}

// ---------------- launch ----------------------------------------------------
extern "C" void kernel_launch(void* const* d_in, const int* in_sizes, int n_in,
                              void* d_out, int out_size) {
    const float* x    = (const float*)d_in[0];
    const int*   ei   = (const int*)  d_in[1];
    const float* ea   = (const float*)d_in[2];
    const float* Wl1  = (const float*)d_in[3];
    const float* bl1  = (const float*)d_in[4];
    const float* Wr1  = (const float*)d_in[5];
    const float* br1  = (const float*)d_in[6];
    const float* We1  = (const float*)d_in[7];
    const float* att1 = (const float*)d_in[8];
    const float* bo1  = (const float*)d_in[9];
    const float* Wl2  = (const float*)d_in[10];
    const float* bl2  = (const float*)d_in[11];
    const float* Wr2  = (const float*)d_in[12];
    const float* br2  = (const float*)d_in[13];
    const float* We2  = (const float*)d_in[14];
    const float* att2 = (const float*)d_in[15];
    const float* bo2  = (const float*)d_in[16];
    const float* Wlin = (const float*)d_in[17];
    const float* blin = (const float*)d_in[18];
    float* out = (float*)d_out;

    float *pxl, *pxr, *ph, *pacc, *psum;
    cudaGetSymbolAddress((void**)&pxl,  g_xl);
    cudaGetSymbolAddress((void**)&pxr,  g_xr);
    cudaGetSymbolAddress((void**)&ph,   g_h);
    cudaGetSymbolAddress((void**)&pacc, g_acc);
    cudaGetSymbolAddress((void**)&psum, g_sum);

    const int TB = 256;
    const int gb_n    = (Nn + TB - 1) / TB;
    const int gb_e    = (Ee + TB - 1) / TB;
    const int gb_nf   = (Nn * 128 + TB - 1) / TB;
    const int gb_warp = (ETOT + 7) / 8;            // 8 edge-warps / block
    const int gb_gemm = (Nn + 127) / 128;
    dim3 grid2(gb_gemm, 2);

    // self-loop attrs
    zero_loop_k<<<gb_n, TB>>>();
    loop_accum_k<<<gb_e, TB>>>(ei, ea);
    loop_fin_k<<<gb_n, TB>>>();

    // ---- layer 1 ----
    gemm2_k<<<grid2, TB>>>(x, Wl1, bl1, pxl, Wr1, br1, pxr, Nn, 0);
    cudaMemsetAsync(pacc, 0, (size_t)Nn * 128 * sizeof(float));
    cudaMemsetAsync(psum, 0, (size_t)Nn * 4 * sizeof(float));
    edge_fused_k<<<gb_warp, TB>>>(ei, ea, We1, att1);
    norm_bias_relu_k<<<gb_nf, TB>>>(bo1);

    // ---- layer 2 ----
    gemm2_k<<<grid2, TB>>>(ph, Wl2, bl2, pxl, Wr2, br2, pxr, Nn, 0);
    cudaMemsetAsync(pacc, 0, (size_t)Nn * 128 * sizeof(float));
    cudaMemsetAsync(psum, 0, (size_t)Nn * 4 * sizeof(float));
    edge_fused_k<<<gb_warp, TB>>>(ei, ea, We2, att2);
    norm_bias_relu_k<<<gb_nf, TB>>>(bo2);

    // ---- final linear + relu -> d_out ----
    dim3 grid1(gb_gemm, 1);
    gemm2_k<<<grid1, TB>>>(ph, Wlin, blin, out, Wlin, blin, out, Nn, 1);
}

// round 3
// speedup vs baseline: 3.1900x; 2.0828x over previous
#include <cuda_runtime.h>
#include <cstdint>

#define Nn 50000
#define Ee 800000
#define ETOT (Ee + Nn)
#define NEG 0.2f
#define NB_SCAN ((Nn + 255) / 256)

// ---------------- scratch (device globals; no runtime allocation) ----------
__device__ float g_xl[(size_t)Nn * 128];
__device__ float g_xr[(size_t)Nn * 128];
__device__ float g_h[(size_t)Nn * 128];
__device__ float g_lsum[Nn];
__device__ float g_lattr[Nn];
__device__ int   g_cnt[Nn];
__device__ int   g_rowptr[Nn + 1];
__device__ int   g_wp[Nn];
__device__ int   g_esrc[ETOT];
__device__ float g_eattr[ETOT];
__device__ int   g_bsum[NB_SCAN];
__device__ int   g_boff[NB_SCAN];

// ---------------- helpers ---------------------------------------------------
__device__ __forceinline__ float lrelu(float v) { return (v > 0.f) ? v : NEG * v; }

__device__ __forceinline__ uint32_t to_tf32(float f) {
    uint32_t u;
    asm("cvt.rna.tf32.f32 %0, %1;" : "=r"(u) : "f"(f));
    return u;
}
__device__ __forceinline__ void cp16(void* s, const void* g, bool pred) {
    unsigned sa = (unsigned)__cvta_generic_to_shared(s);
    int sz = pred ? 16 : 0;
    asm volatile("cp.async.cg.shared.global [%0], [%1], 16, %2;\n"
                 :: "r"(sa), "l"(g), "r"(sz));
}
__device__ __forceinline__ void cp_commit() { asm volatile("cp.async.commit_group;\n"); }
__device__ __forceinline__ void cp_wait()   { asm volatile("cp.async.wait_group 0;\n"); }

__device__ __forceinline__ void mma_tf32(float c[4], uint32_t a0, uint32_t a1,
                                         uint32_t a2, uint32_t a3,
                                         uint32_t b0, uint32_t b1) {
    asm volatile(
        "mma.sync.aligned.m16n8k8.row.col.f32.tf32.tf32.f32 "
        "{%0,%1,%2,%3}, {%4,%5,%6,%7}, {%8,%9}, {%0,%1,%2,%3};\n"
        : "+f"(c[0]), "+f"(c[1]), "+f"(c[2]), "+f"(c[3])
        : "r"(a0), "r"(a1), "r"(a2), "r"(a3), "r"(b0), "r"(b1));
}

// ================= CSR build =================================================
__global__ void init_csr_k() {
    int i = blockIdx.x * blockDim.x + threadIdx.x;
    if (i < Nn) { g_cnt[i] = 1; g_lsum[i] = 0.f; }   // 1 = self loop
}
__global__ void hist_k(const int* __restrict__ ei, const float* __restrict__ ea) {
    int e = blockIdx.x * blockDim.x + threadIdx.x;
    if (e < Ee) {
        int dst = ei[Ee + e];
        atomicAdd(&g_cnt[dst], 1);
        atomicAdd(&g_lsum[dst], ea[e]);
    }
}
__global__ void scan1_k() {
    __shared__ int s[256];
    int t = threadIdx.x;
    int i = blockIdx.x * 256 + t;
    int v = (i < Nn) ? g_cnt[i] : 0;
    s[t] = v; __syncthreads();
#pragma unroll
    for (int off = 1; off < 256; off <<= 1) {
        int add = (t >= off) ? s[t - off] : 0;
        __syncthreads();
        s[t] += add;
        __syncthreads();
    }
    if (i < Nn) g_rowptr[i] = s[t] - v;          // exclusive within block
    if (t == 255) g_bsum[blockIdx.x] = s[255];
}
__global__ void scan2_k() {
    __shared__ int s[256];
    int t = threadIdx.x;
    int v = (t < NB_SCAN) ? g_bsum[t] : 0;
    s[t] = v; __syncthreads();
#pragma unroll
    for (int off = 1; off < 256; off <<= 1) {
        int add = (t >= off) ? s[t - off] : 0;
        __syncthreads();
        s[t] += add;
        __syncthreads();
    }
    if (t < NB_SCAN) g_boff[t] = s[t] - v;       // exclusive
}
__global__ void scan3_k() {
    int i = blockIdx.x * blockDim.x + threadIdx.x;
    if (i >= Nn) return;
    int rp = g_rowptr[i] + g_boff[i >> 8];
    g_rowptr[i] = rp;
    g_wp[i] = rp;
    int inc = g_cnt[i] - 1;                      // incoming edges
    g_lattr[i] = (inc > 0) ? g_lsum[i] / (float)inc : 0.f;
    if (i == 0) g_rowptr[Nn] = ETOT;
}
__global__ void scatter_k(const int* __restrict__ ei, const float* __restrict__ ea) {
    int e = blockIdx.x * blockDim.x + threadIdx.x;
    if (e < Ee) {
        int dst = ei[Ee + e];
        int pos = atomicAdd(&g_wp[dst], 1);
        g_esrc[pos] = ei[e];
        g_eattr[pos] = ea[e];
    }
}
__global__ void selfloop_k() {
    int n = blockIdx.x * blockDim.x + threadIdx.x;
    if (n < Nn) {
        int pos = g_rowptr[n + 1] - 1;           // last slot reserved for loop
        g_esrc[pos] = n;
        g_eattr[pos] = g_lattr[n];
    }
}

// ================= tf32 tensor-core GEMM ====================================
// C[M][128] = A[M][128] @ W[128][128] + bias; blockIdx.y selects (W0/C0, W1/C1).
// Block: 256 thr (8 warps, 4x2), block tile 128x128, warp tile 32x64,
// mma m16n8k8 tf32, cp.async double-buffered k-chunks of 32.
#define ASTRIDE 36
#define BSTRIDE 136
#define ASZ (128 * ASTRIDE)
#define BSZ (32 * BSTRIDE)
#define GEMM_SMEM ((ASZ + BSZ) * 2 * 4)

__global__ void __launch_bounds__(256, 2)
gemm_tc_k(const float* __restrict__ A,
          const float* __restrict__ W0, const float* __restrict__ b0, float* __restrict__ C0,
          const float* __restrict__ W1, const float* __restrict__ b1, float* __restrict__ C1,
          int M, int relu) {
    const float* W    = blockIdx.y ? W1 : W0;
    const float* bias = blockIdx.y ? b1 : b0;
    float*       Cm   = blockIdx.y ? C1 : C0;

    extern __shared__ float sm[];
    float* As[2] = { sm, sm + ASZ };
    float* Bs[2] = { sm + 2 * ASZ, sm + 2 * ASZ + BSZ };

    const int t = threadIdx.x;
    const int lane = t & 31;
    const int wid = t >> 5;
    const int warp_m = wid & 3;        // 0..3 -> 32-row slices
    const int warp_n = wid >> 2;       // 0..1 -> 64-col slices
    const int row0 = blockIdx.x * 128;

    // global load mapping
    const int a_row = t >> 1;                 // 0..127
    const int a_colb = (t & 1) * 16;          // 0 / 16
    const int b_k = t >> 3;                   // 0..31
    const int b_nb = (t & 7) * 16;            // 0..112
    const bool a_ok = (row0 + a_row) < M;
    const float* Arow = A + (size_t)(row0 + a_row) * 128;

    float acc[2][8][4];
#pragma unroll
    for (int i = 0; i < 2; i++)
#pragma unroll
        for (int j = 0; j < 8; j++)
#pragma unroll
            for (int k = 0; k < 4; k++) acc[i][j][k] = 0.f;

    // preload chunk 0
#pragma unroll
    for (int q = 0; q < 4; q++) {
        cp16(&As[0][a_row * ASTRIDE + a_colb + q * 4], Arow + a_colb + q * 4, a_ok);
        cp16(&Bs[0][b_k * BSTRIDE + b_nb + q * 4], W + (size_t)b_k * 128 + b_nb + q * 4, true);
    }
    cp_commit();

    int buf = 0;
    for (int c = 0; c < 4; c++) {
        cp_wait();
        __syncthreads();
        if (c < 3) {
            int k0 = (c + 1) * 32;
            int nb = buf ^ 1;
#pragma unroll
            for (int q = 0; q < 4; q++) {
                cp16(&As[nb][a_row * ASTRIDE + a_colb + q * 4], Arow + k0 + a_colb + q * 4, a_ok);
                cp16(&Bs[nb][b_k * BSTRIDE + b_nb + q * 4], W + (size_t)(k0 + b_k) * 128 + b_nb + q * 4, true);
            }
            cp_commit();
        }
        // compute on buf
        const float* as = As[buf];
        const float* bs = Bs[buf];
        const int ar = warp_m * 32 + (lane >> 2);
        const int ac = lane & 3;
        const int bn = warp_n * 64 + (lane >> 2);
        const int bk = lane & 3;
#pragma unroll
        for (int ks = 0; ks < 4; ks++) {
            uint32_t af[2][4];
#pragma unroll
            for (int mt = 0; mt < 2; mt++) {
                const float* ap = as + (ar + mt * 16) * ASTRIDE + ks * 8 + ac;
                af[mt][0] = to_tf32(ap[0]);
                af[mt][1] = to_tf32(ap[8 * ASTRIDE]);
                af[mt][2] = to_tf32(ap[4]);
                af[mt][3] = to_tf32(ap[8 * ASTRIDE + 4]);
            }
#pragma unroll
            for (int nt = 0; nt < 8; nt++) {
                const float* bp = bs + (ks * 8 + bk) * BSTRIDE + bn + nt * 8;
                uint32_t bf0 = to_tf32(bp[0]);
                uint32_t bf1 = to_tf32(bp[4 * BSTRIDE]);
                mma_tf32(acc[0][nt], af[0][0], af[0][1], af[0][2], af[0][3], bf0, bf1);
                mma_tf32(acc[1][nt], af[1][0], af[1][1], af[1][2], af[1][3], bf0, bf1);
            }
        }
        __syncthreads();
        buf ^= 1;
    }

    // epilogue
    const int crow = row0 + warp_m * 32 + (lane >> 2);
    const int ccol0 = warp_n * 64 + (lane & 3) * 2;
#pragma unroll
    for (int nt = 0; nt < 8; nt++) {
        int col = ccol0 + nt * 8;
        float bx = bias[col], by = bias[col + 1];
#pragma unroll
        for (int mt = 0; mt < 2; mt++) {
            int r0 = crow + mt * 16;
            float v0 = acc[mt][nt][0] + bx, v1 = acc[mt][nt][1] + by;
            float v2 = acc[mt][nt][2] + bx, v3 = acc[mt][nt][3] + by;
            if (relu) {
                v0 = fmaxf(v0, 0.f); v1 = fmaxf(v1, 0.f);
                v2 = fmaxf(v2, 0.f); v3 = fmaxf(v3, 0.f);
            }
            if (r0 < M)     *(float2*)(Cm + (size_t)r0 * 128 + col)       = make_float2(v0, v1);
            if (r0 + 8 < M) *(float2*)(Cm + (size_t)(r0 + 8) * 128 + col) = make_float2(v2, v3);
        }
    }
}

// ================= per-node fused GAT layer =================================
// One warp per dst node: loop in-edges, logit -> exp -> register aggregate.
__global__ void __launch_bounds__(256)
node_agg_k(const float* __restrict__ We, const float* __restrict__ att,
           const float* __restrict__ bo) {
    int n = (blockIdx.x * blockDim.x + threadIdx.x) >> 5;
    int lane = threadIdx.x & 31;
    if (n >= Nn) return;

    float4 br  = *(const float4*)(g_xr + (size_t)n * 128 + lane * 4);
    float4 w4  = *(const float4*)(We + lane * 4);
    float4 at4 = *(const float4*)(att + lane * 4);

    float4 acc = make_float4(0.f, 0.f, 0.f, 0.f);
    float ssum = 0.f;

    int beg = g_rowptr[n], end = g_rowptr[n + 1];
    for (int j = beg; j < end; j++) {
        int src = g_esrc[j];
        float attr = g_eattr[j];
        float4 a = *(const float4*)(g_xl + (size_t)src * 128 + lane * 4);
        float m0 = lrelu(a.x + br.x + attr * w4.x);
        float m1 = lrelu(a.y + br.y + attr * w4.y);
        float m2 = lrelu(a.z + br.z + attr * w4.z);
        float m3 = lrelu(a.w + br.w + attr * w4.w);
        float p = m0 * at4.x + m1 * at4.y + m2 * at4.z + m3 * at4.w;
        p += __shfl_xor_sync(0xFFFFFFFFu, p, 1);
        p += __shfl_xor_sync(0xFFFFFFFFu, p, 2);
        p += __shfl_xor_sync(0xFFFFFFFFu, p, 4);
        float e = __expf(p);
        acc.x = fmaf(e, a.x, acc.x);
        acc.y = fmaf(e, a.y, acc.y);
        acc.z = fmaf(e, a.z, acc.z);
        acc.w = fmaf(e, a.w, acc.w);
        ssum += e;
    }
    float inv = 1.f / (ssum + 1e-16f);
    float4 bo4 = *(const float4*)(bo + lane * 4);
    float4 o;
    o.x = fmaxf(acc.x * inv + bo4.x, 0.f);
    o.y = fmaxf(acc.y * inv + bo4.y, 0.f);
    o.z = fmaxf(acc.z * inv + bo4.z, 0.f);
    o.w = fmaxf(acc.w * inv + bo4.w, 0.f);
    *(float4*)(g_h + (size_t)n * 128 + lane * 4) = o;
}

// ================= launch ===================================================
extern "C" void kernel_launch(void* const* d_in, const int* in_sizes, int n_in,
                              void* d_out, int out_size) {
    const float* x    = (const float*)d_in[0];
    const int*   ei   = (const int*)  d_in[1];
    const float* ea   = (const float*)d_in[2];
    const float* Wl1  = (const float*)d_in[3];
    const float* bl1  = (const float*)d_in[4];
    const float* Wr1  = (const float*)d_in[5];
    const float* br1  = (const float*)d_in[6];
    const float* We1  = (const float*)d_in[7];
    const float* att1 = (const float*)d_in[8];
    const float* bo1  = (const float*)d_in[9];
    const float* Wl2  = (const float*)d_in[10];
    const float* bl2  = (const float*)d_in[11];
    const float* Wr2  = (const float*)d_in[12];
    const float* br2  = (const float*)d_in[13];
    const float* We2  = (const float*)d_in[14];
    const float* att2 = (const float*)d_in[15];
    const float* bo2  = (const float*)d_in[16];
    const float* Wlin = (const float*)d_in[17];
    const float* blin = (const float*)d_in[18];
    float* out = (float*)d_out;

    float *pxl, *pxr, *ph;
    cudaGetSymbolAddress((void**)&pxl, g_xl);
    cudaGetSymbolAddress((void**)&pxr, g_xr);
    cudaGetSymbolAddress((void**)&ph,  g_h);

    static int smem_set = 0;
    if (!smem_set) {
        cudaFuncSetAttribute(gemm_tc_k, cudaFuncAttributeMaxDynamicSharedMemorySize, GEMM_SMEM);
        smem_set = 1;
    }

    const int TB = 256;
    const int gb_n  = (Nn + TB - 1) / TB;
    const int gb_e  = (Ee + TB - 1) / TB;
    const int gb_gemm = (Nn + 127) / 128;
    const int gb_node = (Nn * 32 + TB - 1) / TB;   // one warp per node
    dim3 grid2(gb_gemm, 2), grid1(gb_gemm, 1);

    // ---- CSR build (by dst) + self-loop attrs ----
    init_csr_k<<<gb_n, TB>>>();
    hist_k<<<gb_e, TB>>>(ei, ea);
    scan1_k<<<NB_SCAN, 256>>>();
    scan2_k<<<1, 256>>>();
    scan3_k<<<gb_n, TB>>>();
    scatter_k<<<gb_e, TB>>>(ei, ea);
    selfloop_k<<<gb_n, TB>>>();

    // ---- layer 1 ----
    gemm_tc_k<<<grid2, TB, GEMM_SMEM>>>(x, Wl1, bl1, pxl, Wr1, br1, pxr, Nn, 0);
    node_agg_k<<<gb_node, TB>>>(We1, att1, bo1);

    // ---- layer 2 ----
    gemm_tc_k<<<grid2, TB, GEMM_SMEM>>>(ph, Wl2, bl2, pxl, Wr2, br2, pxr, Nn, 0);
    node_agg_k<<<gb_node, TB>>>(We2, att2, bo2);

    // ---- final linear + relu -> d_out ----
    gemm_tc_k<<<grid1, TB, GEMM_SMEM>>>(ph, Wlin, blin, out, Wlin, blin, out, Nn, 1);
}